// round 12
// baseline (speedup 1.0000x reference)
#include <cuda_runtime.h>
#include <cstdint>

#define N_NODES    200000
#define N_CHILD    32
#define N_LAYERS   8
#define N_CHUNKS   4
#define CHUNK      50000          // floats per chunk: 200KB smem; 4*50000=200000
#define N_RANGES   37
#define RANGE_SZ   5408           // 37*5408 >= 200000, multiple of 8
#define THREADS    1024

// Ping-pong layer-value buffers (src/dst distinct — no grid sync in a launch).
__device__ float g_bufA[N_NODES];
__device__ float g_bufB[N_NODES];
// Per-chunk partial arrays: contiguous, single-writer cache lines.
// (NOT float4-per-node: cross-SM 4B component stores into shared 16B slots
// cost +18us/layer in R10.)
__device__ float g_partial[N_CHUNKS][N_NODES];
// Monotonic arrival counters (replay-safe via mod-4; zero-init at load;
// each layer-launch adds exactly 4 per range).
__device__ unsigned g_arrive[N_RANGES];

// Grid = 37 ranges x 4 chunks = 148 blocks, free scheduling (NO clusters).
// Block (range,chunk): stages its 50K-float chunk to smem, computes chunk-c
// partial sums for all nodes of its range via predicated LDS (R4's proven
// loop, verbatim — no prefetch), stores to g_partial[chunk][*], then
// publishes via the cooperative-groups release pattern: __syncthreads()
// followed by fence+atomicAdd from thread 0 ONLY (R9 fenced from all 1024
// threads — removed). The 4th arriver acquire-fences and combines the range
// inline: w*sum + activation -> dst. Values fully deterministic.
__global__ void __launch_bounds__(THREADS, 1) layer_kernel(
    const float* __restrict__ src,     // previous layer values [N_NODES]
    float*       __restrict__ dst,     // this layer's outputs   [N_NODES]
    const int4*  __restrict__ cidx,    // this layer's indices as int4
    const int*   __restrict__ fids,    // this layer's fun_ids
    const float* __restrict__ wptr)
{
    extern __shared__ float sval[];    // CHUNK floats

    const int chunk = blockIdx.x & (N_CHUNKS - 1);
    const int range = blockIdx.x >> 2;
    const int cbase = chunk * CHUNK;
    const int range_start = range * RANGE_SZ;

    // ---- Phase 1: stage chunk (coalesced float4; src is L2-resident) ----
    {
        const float4* s4 = (const float4*)(src + cbase);
        float4* d4 = (float4*)sval;
        for (int i = threadIdx.x; i < CHUNK / 4; i += THREADS)
            d4[i] = s4[i];
    }
    __syncthreads();

    // ---- Phase 2: chunk-c partial sums (R4's proven loop, verbatim) ----
    const int warp = threadIdx.x >> 5;
    const int lane = threadIdx.x & 31;

    for (int t = warp; t * 8 < RANGE_SZ; t += THREADS / 32) {
        const int node0 = range_start + t * 8;
        if (node0 >= N_NODES) break;

        const size_t ibase = (size_t)node0 * (N_CHILD / 4);
        const int4 cA = cidx[ibase + lane];
        const int4 cB = cidx[ibase + 32 + lane];

        float sA = 0.0f, sB = 0.0f;
        {
            unsigned r;
            r = (unsigned)(cA.x - cbase); if (r < CHUNK) sA += sval[r];
            r = (unsigned)(cA.y - cbase); if (r < CHUNK) sA += sval[r];
            r = (unsigned)(cA.z - cbase); if (r < CHUNK) sA += sval[r];
            r = (unsigned)(cA.w - cbase); if (r < CHUNK) sA += sval[r];
            r = (unsigned)(cB.x - cbase); if (r < CHUNK) sB += sval[r];
            r = (unsigned)(cB.y - cbase); if (r < CHUNK) sB += sval[r];
            r = (unsigned)(cB.z - cbase); if (r < CHUNK) sB += sval[r];
            r = (unsigned)(cB.w - cbase); if (r < CHUNK) sB += sval[r];
        }

        sA += __shfl_down_sync(0xffffffffu, sA, 4);
        sB += __shfl_down_sync(0xffffffffu, sB, 4);
        sA += __shfl_down_sync(0xffffffffu, sA, 2);
        sB += __shfl_down_sync(0xffffffffu, sB, 2);
        sA += __shfl_down_sync(0xffffffffu, sA, 1);
        sB += __shfl_down_sync(0xffffffffu, sB, 1);

        if ((lane & 7) == 0) {
            const int g = lane >> 3;
            g_partial[chunk][node0 + g]     = sA;
            g_partial[chunk][node0 + 4 + g] = sB;
        }
    }

    // ---- Phase 3: publish (release from ONE thread after bar.sync) ----
    __syncthreads();                    // intra-block happens-before for stores

    __shared__ int s_combine;
    if (threadIdx.x == 0) {
        __threadfence();                // release: push this block's partials
        const unsigned old = atomicAdd(&g_arrive[range], 1u);
        s_combine = ((old & 3u) == 3u) ? 1 : 0;
    }
    __syncthreads();

    // ---- Phase 4: 4th arriver combines this range ----
    if (s_combine) {
        __threadfence();                // acquire: see peers' partial stores
        const float wv = *wptr;
        for (int i = threadIdx.x; i < RANGE_SZ; i += THREADS) {
            const int n = range_start + i;
            if (n >= N_NODES) break;
            const float s = (g_partial[0][n] + g_partial[1][n])
                          + (g_partial[2][n] + g_partial[3][n]);
            const float x = wv * s;
            const int fid = __ldg(fids + n);
            float r;
            if      (fid == 0) r = tanhf(x);
            else if (fid == 1) r = 1.0f / (1.0f + expf(-x));
            else if (fid == 2) r = fmaxf(x, 0.0f);
            else               r = x;
            dst[n] = r;
        }
    }
}

extern "C" void kernel_launch(void* const* d_in, const int* in_sizes, int n_in,
                              void* d_out, int out_size)
{
    const float* X    = (const float*)d_in[0];
    const float* w    = (const float*)d_in[1];
    const int*   cidx = (const int*)  d_in[2];  // [N_LAYERS, N_NODES, N_CHILD]
    const int*   fids = (const int*)  d_in[3];  // [N_LAYERS, N_NODES]
    float*       out  = (float*)d_out;

    float* bufA = nullptr;
    float* bufB = nullptr;
    cudaGetSymbolAddress((void**)&bufA, g_bufA);
    cudaGetSymbolAddress((void**)&bufB, g_bufB);

    const size_t SMEM_BYTES = (size_t)CHUNK * sizeof(float);  // 200KB
    cudaFuncSetAttribute(layer_kernel,
                         cudaFuncAttributeMaxDynamicSharedMemorySize,
                         (int)SMEM_BYTES);

    // Ping-pong: layer i reads ins[i], writes outs[i] (always distinct).
    const float* ins[N_LAYERS]  = { X, bufA, bufB, bufA, bufB, bufA, bufB, bufA };
    float*       outs[N_LAYERS] = { bufA, bufB, bufA, bufB, bufA, bufB, bufA, out };

    const int grid = N_RANGES * N_CHUNKS;   // 148 blocks, one wave

    for (int l = 0; l < N_LAYERS; l++) {
        const int4* layer_cidx =
            (const int4*)(cidx + (size_t)l * N_NODES * N_CHILD);
        const int* layer_fids = fids + (size_t)l * N_NODES;

        layer_kernel<<<grid, THREADS, SMEM_BYTES>>>(
            ins[l], outs[l], layer_cidx, layer_fids, w);
    }
}

// round 14
// speedup vs baseline: 1.2095x; 1.2095x over previous
#include <cuda_runtime.h>
#include <cstdint>

#define N_NODES    200000
#define N_CHILD    32
#define N_LAYERS   8
#define N_CHUNKS   4
#define CHUNK      50000          // floats per chunk: 200KB smem; 4*50000=200000
#define N_RANGES   37
#define RANGE_SZ   5408           // 37*5408 >= 200000, multiple of 8
#define THREADS    1024
#define STAGE_BYTES (CHUNK * 4)   // 200000 bytes, multiple of 16

// Ping-pong layer-value buffers (src/dst distinct — no grid sync in a launch).
__device__ float g_bufA[N_NODES];
__device__ float g_bufB[N_NODES];
// Per-chunk partial arrays: contiguous, single-writer cache lines.
__device__ float g_partial[N_CHUNKS][N_NODES];

__device__ __forceinline__ uint32_t smem_u32(const void* p) {
    uint32_t a;
    asm("{ .reg .u64 t; cvta.to.shared.u64 t, %1; cvt.u32.u64 %0, t; }"
        : "=r"(a) : "l"(p));
    return a;
}

// ---------------- Gather ----------------
// Grid = 37 ranges x 4 chunks = 148 blocks (one wave, free scheduling).
// Block (range,chunk): DMA-stages its 50K-float chunk into smem via ONE
// cp.async.bulk (replaces ~780 LDG/STS warp-ops), then computes the chunk's
// partial sum for every node of its range via predicated LDS.
// 8 nodes/warp-task via two coalesced int4 loads per lane; reduction uses a
// 4-shfl butterfly (merge A/B node-sets at xor-4, then xor-2, xor-1) instead
// of the previous 6-shfl two-tree form.
__global__ void __launch_bounds__(THREADS, 1) gather_kernel(
    const float* __restrict__ src,     // layer-input values [N_NODES]
    const int4*  __restrict__ cidx)    // this layer's indices as int4
{
    extern __shared__ float sval[];    // CHUNK floats
    __shared__ __align__(8) unsigned long long s_mbar;

    const int chunk = blockIdx.x & (N_CHUNKS - 1);
    const int range = blockIdx.x >> 2;
    const int cbase = chunk * CHUNK;
    const int range_start = range * RANGE_SZ;

    // ---- Stage chunk via bulk async DMA ----
    const uint32_t mbar = smem_u32(&s_mbar);
    if (threadIdx.x == 0) {
        asm volatile("mbarrier.init.shared.b64 [%0], %1;"
                     :: "r"(mbar), "r"(1) : "memory");
    }
    __syncthreads();                   // init visible before anyone polls
    if (threadIdx.x == 0) {
        asm volatile("mbarrier.arrive.expect_tx.shared.b64 _, [%0], %1;"
                     :: "r"(mbar), "r"(STAGE_BYTES) : "memory");
        asm volatile(
            "cp.async.bulk.shared::cluster.global.mbarrier::complete_tx::bytes "
            "[%0], [%1], %2, [%3];"
            :: "r"(smem_u32(sval)), "l"(src + cbase),
               "r"(STAGE_BYTES), "r"(mbar) : "memory");
    }
    // Wait for DMA completion (phase 0).
    {
        uint32_t done;
        asm volatile(
            "{\n\t.reg .pred p;\n\t"
            "mbarrier.try_wait.parity.shared.b64 p, [%1], 0;\n\t"
            "selp.b32 %0, 1, 0, p;\n\t}"
            : "=r"(done) : "r"(mbar) : "memory");
        while (!done) {
            asm volatile(
                "{\n\t.reg .pred p;\n\t"
                "mbarrier.try_wait.parity.shared.b64 p, [%1], 0;\n\t"
                "selp.b32 %0, 1, 0, p;\n\t}"
                : "=r"(done) : "r"(mbar) : "memory");
        }
    }

    const int warp = threadIdx.x >> 5;
    const int lane = threadIdx.x & 31;

    for (int t = warp; t * 8 < RANGE_SZ; t += THREADS / 32) {
        const int node0 = range_start + t * 8;
        if (node0 >= N_NODES) break;

        // Coalesced: lane k reads int4 k (nodes 0-3) and int4 32+k (nodes 4-7).
        const size_t ibase = (size_t)node0 * (N_CHILD / 4);
        const int4 cA = cidx[ibase + lane];
        const int4 cB = cidx[ibase + 32 + lane];

        float sA = 0.0f, sB = 0.0f;
        {
            unsigned r;
            r = (unsigned)(cA.x - cbase); if (r < CHUNK) sA += sval[r];
            r = (unsigned)(cA.y - cbase); if (r < CHUNK) sA += sval[r];
            r = (unsigned)(cA.z - cbase); if (r < CHUNK) sA += sval[r];
            r = (unsigned)(cA.w - cbase); if (r < CHUNK) sA += sval[r];
            r = (unsigned)(cB.x - cbase); if (r < CHUNK) sB += sval[r];
            r = (unsigned)(cB.y - cbase); if (r < CHUNK) sB += sval[r];
            r = (unsigned)(cB.z - cbase); if (r < CHUNK) sB += sval[r];
            r = (unsigned)(cB.w - cbase); if (r < CHUNK) sB += sval[r];
        }

        // 4-shfl butterfly: merge A/B sets at xor-4, finish both at xor-2/1.
        // Lanes g*8..g*8+3 carry node (node0+g); lanes g*8+4..+7 carry
        // node (node0+4+g). After xor-2 and xor-1, lane g*8 holds node A's
        // sum and lane g*8+4 holds node B's.
        const float eA = __shfl_xor_sync(0xffffffffu, sA, 4);
        const float eB = __shfl_xor_sync(0xffffffffu, sB, 4);
        float v = (lane & 4) ? (sB + eB) : (sA + eA);
        v += __shfl_xor_sync(0xffffffffu, v, 2);
        v += __shfl_xor_sync(0xffffffffu, v, 1);

        if ((lane & 3) == 0)
            g_partial[chunk][node0 + (lane >> 3) + (lane & 4)] = v;
    }
}

// ---------------- Combine (R4 verbatim — measured 5.0us) ----------------
__global__ void __launch_bounds__(512) combine_kernel(
    float*       __restrict__ dst,
    const int*   __restrict__ fids,    // this layer's fun_ids
    const float* __restrict__ wptr)
{
    const int n = blockIdx.x * blockDim.x + threadIdx.x;
    if (n >= N_NODES) return;

    const float s = (g_partial[0][n] + g_partial[1][n])
                  + (g_partial[2][n] + g_partial[3][n]);
    const float x = wptr[0] * s;
    const int fid = __ldg(fids + n);
    float r;
    if      (fid == 0) r = tanhf(x);
    else if (fid == 1) r = 1.0f / (1.0f + expf(-x));
    else if (fid == 2) r = fmaxf(x, 0.0f);
    else               r = x;
    dst[n] = r;
}

extern "C" void kernel_launch(void* const* d_in, const int* in_sizes, int n_in,
                              void* d_out, int out_size)
{
    const float* X    = (const float*)d_in[0];
    const float* w    = (const float*)d_in[1];
    const int*   cidx = (const int*)  d_in[2];  // [N_LAYERS, N_NODES, N_CHILD]
    const int*   fids = (const int*)  d_in[3];  // [N_LAYERS, N_NODES]
    float*       out  = (float*)d_out;

    float* bufA = nullptr;
    float* bufB = nullptr;
    cudaGetSymbolAddress((void**)&bufA, g_bufA);
    cudaGetSymbolAddress((void**)&bufB, g_bufB);

    const size_t SMEM_BYTES = (size_t)CHUNK * sizeof(float);  // 200KB
    cudaFuncSetAttribute(gather_kernel,
                         cudaFuncAttributeMaxDynamicSharedMemorySize,
                         (int)SMEM_BYTES);

    // Ping-pong: layer i reads ins[i], writes outs[i] (always distinct).
    const float* ins[N_LAYERS]  = { X, bufA, bufB, bufA, bufB, bufA, bufB, bufA };
    float*       outs[N_LAYERS] = { bufA, bufB, bufA, bufB, bufA, bufB, bufA, out };

    const int gather_grid  = N_RANGES * N_CHUNKS;       // 148
    const int combine_grid = (N_NODES + 511) / 512;     // 391

    for (int l = 0; l < N_LAYERS; l++) {
        const int4* layer_cidx =
            (const int4*)(cidx + (size_t)l * N_NODES * N_CHILD);
        const int* layer_fids = fids + (size_t)l * N_NODES;

        gather_kernel<<<gather_grid, THREADS, SMEM_BYTES>>>(ins[l], layer_cidx);
        combine_kernel<<<combine_grid, 512>>>(outs[l], layer_fids, w);
    }
}